// round 1
// baseline (speedup 1.0000x reference)
#include <cuda_runtime.h>
#include <math.h>

#define B_  4
#define L_  2048
#define D_  512
#define H_  8
#define DH_ 64
#define NTOK (B_ * L_)   // 8192

// Scratch (allocation-free rule: __device__ globals). 4 x 16MB = 64MB.
__device__ float g_q[(size_t)B_ * H_ * L_ * DH_];
__device__ float g_k[(size_t)B_ * H_ * L_ * DH_];
__device__ float g_v[(size_t)B_ * H_ * L_ * DH_];
__device__ float g_o[(size_t)B_ * H_ * L_ * DH_];

// ---------------------------------------------------------------------------
// Fused QKV projection: Y[n, j] = sum_d X[n,d] * W[j,d] + bias[j]
// written directly into (B,H,L,DH) head layout.
// 64x64 tile, 256 threads, 4x4 register tile, K-chunk 32.
// ---------------------------------------------------------------------------
__global__ __launch_bounds__(256) void proj_kernel(
    const float* __restrict__ Xq, const float* __restrict__ Xk, const float* __restrict__ Xv,
    const float* __restrict__ Wq, const float* __restrict__ Wk, const float* __restrict__ Wv,
    const float* __restrict__ bq, const float* __restrict__ bk, const float* __restrict__ bv)
{
    __shared__ float As[32][68];
    __shared__ float Ws[32][68];

    const float *X, *W, *bias;
    float* Y;
    if (blockIdx.z == 0)      { X = Xq; W = Wq; bias = bq; Y = g_q; }
    else if (blockIdx.z == 1) { X = Xk; W = Wk; bias = bk; Y = g_k; }
    else                      { X = Xv; W = Wv; bias = bv; Y = g_v; }

    const int t  = threadIdx.x;
    const int tr = t >> 4;
    const int tc = t & 15;
    const int m0 = blockIdx.x * 64;
    const int n0 = blockIdx.y * 64;

    float acc[4][4] = {};

    for (int k0 = 0; k0 < D_; k0 += 32) {
        #pragma unroll
        for (int rep = 0; rep < 2; rep++) {
            int id  = t + rep * 256;
            int row = id >> 3;           // 0..63
            int kg  = (id & 7) << 2;     // 0,4,...,28
            float4 xa = *(const float4*)(X + (size_t)(m0 + row) * D_ + k0 + kg);
            float4 wa = *(const float4*)(W + (size_t)(n0 + row) * D_ + k0 + kg);
            As[kg + 0][row] = xa.x; As[kg + 1][row] = xa.y;
            As[kg + 2][row] = xa.z; As[kg + 3][row] = xa.w;
            Ws[kg + 0][row] = wa.x; Ws[kg + 1][row] = wa.y;
            Ws[kg + 2][row] = wa.z; Ws[kg + 3][row] = wa.w;
        }
        __syncthreads();
        #pragma unroll
        for (int kk = 0; kk < 32; kk++) {
            float4 a4 = *(const float4*)&As[kk][tr << 2];
            float4 b4 = *(const float4*)&Ws[kk][tc << 2];
            float a[4] = {a4.x, a4.y, a4.z, a4.w};
            float b[4] = {b4.x, b4.y, b4.z, b4.w};
            #pragma unroll
            for (int i = 0; i < 4; i++)
                #pragma unroll
                for (int j = 0; j < 4; j++)
                    acc[i][j] = fmaf(a[i], b[j], acc[i][j]);
        }
        __syncthreads();
    }

    #pragma unroll
    for (int i = 0; i < 4; i++) {
        int n  = m0 + (tr << 2) + i;
        int bb = n >> 11;              // n / 2048
        int ll = n & (L_ - 1);
        #pragma unroll
        for (int j = 0; j < 4; j++) {
            int col = n0 + (tc << 2) + j;
            int hh  = col >> 6;
            int dh  = col & 63;
            Y[(((size_t)bb * H_ + hh) * L_ + ll) * DH_ + dh] = acc[i][j] + bias[col];
        }
    }
}

// ---------------------------------------------------------------------------
// Output projection: gathers (B,H,L,DH) -> (B*L, D), GEMM with fc_w, + bias.
// ---------------------------------------------------------------------------
__global__ __launch_bounds__(256) void fc_kernel(
    const float* __restrict__ Wf, const float* __restrict__ bf, float* __restrict__ out)
{
    __shared__ float As[32][68];
    __shared__ float Ws[32][68];

    const int t  = threadIdx.x;
    const int tr = t >> 4;
    const int tc = t & 15;
    const int m0 = blockIdx.x * 64;
    const int n0 = blockIdx.y * 64;

    float acc[4][4] = {};

    for (int k0 = 0; k0 < D_; k0 += 32) {
        #pragma unroll
        for (int rep = 0; rep < 2; rep++) {
            int id  = t + rep * 256;
            int row = id >> 3;
            int kg  = (id & 7) << 2;
            int n   = m0 + row;
            int bb  = n >> 11;
            int ll  = n & (L_ - 1);
            int d   = k0 + kg;
            int hh  = d >> 6;
            int dh  = d & 63;
            float4 xa = *(const float4*)(g_o + (((size_t)bb * H_ + hh) * L_ + ll) * DH_ + dh);
            float4 wa = *(const float4*)(Wf + (size_t)(n0 + row) * D_ + k0 + kg);
            As[kg + 0][row] = xa.x; As[kg + 1][row] = xa.y;
            As[kg + 2][row] = xa.z; As[kg + 3][row] = xa.w;
            Ws[kg + 0][row] = wa.x; Ws[kg + 1][row] = wa.y;
            Ws[kg + 2][row] = wa.z; Ws[kg + 3][row] = wa.w;
        }
        __syncthreads();
        #pragma unroll
        for (int kk = 0; kk < 32; kk++) {
            float4 a4 = *(const float4*)&As[kk][tr << 2];
            float4 b4 = *(const float4*)&Ws[kk][tc << 2];
            float a[4] = {a4.x, a4.y, a4.z, a4.w};
            float b[4] = {b4.x, b4.y, b4.z, b4.w};
            #pragma unroll
            for (int i = 0; i < 4; i++)
                #pragma unroll
                for (int j = 0; j < 4; j++)
                    acc[i][j] = fmaf(a[i], b[j], acc[i][j]);
        }
        __syncthreads();
    }

    #pragma unroll
    for (int i = 0; i < 4; i++) {
        int n = m0 + (tr << 2) + i;
        #pragma unroll
        for (int j = 0; j < 4; j++) {
            int col = n0 + (tc << 2) + j;
            out[(size_t)n * D_ + col] = acc[i][j] + bf[col];
        }
    }
}

// ---------------------------------------------------------------------------
// 4x4 register-tile of dot products over a 64-length K dimension from smem.
// ---------------------------------------------------------------------------
__device__ __forceinline__ void tile_dot(const float* __restrict__ A0, int sA,
                                         const float* __restrict__ B0, int sB,
                                         float acc[4][4])
{
    #pragma unroll
    for (int kk = 0; kk < 64; kk += 4) {
        float a[4][4], b[4][4];
        #pragma unroll
        for (int i = 0; i < 4; i++) {
            float4 v = *(const float4*)(A0 + i * sA + kk);
            a[i][0] = v.x; a[i][1] = v.y; a[i][2] = v.z; a[i][3] = v.w;
        }
        #pragma unroll
        for (int j = 0; j < 4; j++) {
            float4 v = *(const float4*)(B0 + j * sB + kk);
            b[j][0] = v.x; b[j][1] = v.y; b[j][2] = v.z; b[j][3] = v.w;
        }
        #pragma unroll
        for (int i = 0; i < 4; i++)
            #pragma unroll
            for (int j = 0; j < 4; j++)
                #pragma unroll
                for (int c = 0; c < 4; c++)
                    acc[i][j] = fmaf(a[i][c], b[j][c], acc[i][j]);
    }
}

// ---------------------------------------------------------------------------
// Flash-style causal attention with relative position term.
// S[l,m] = (q[l]·k[m] + q[l]·E[L-1-l+m]) / 8, causal softmax, O = P·V.
// Per key tile: QE strip of 128 E-rows computed as two 64x64 GEMMs;
// gather S2[li,mi] = QEb[li][63 - li + mi].
// smem: Qs[64][68] | Bs[64][72] (E/K/V, reused) | QEb[64][132] (cols 0..63
// reused as P after the gather barrier).
// ---------------------------------------------------------------------------
__global__ __launch_bounds__(256) void attn_kernel(const float* __restrict__ E)
{
    extern __shared__ float sm[];
    float* Qs  = sm;                          // 64 x 68
    float* Bs  = sm + 64 * 68;                // 64 x 72
    float* QEb = sm + 64 * 68 + 64 * 72;      // 64 x 132

    const int t  = threadIdx.x;
    const int tr = t >> 4;
    const int tc = t & 15;
    const int qt = (int)(gridDim.x - 1) - (int)blockIdx.x;  // heavy tiles first
    const int l0 = qt * 64;
    const int bh = blockIdx.y;

    const float* qp = g_q + (size_t)bh * L_ * DH_;
    const float* kp = g_k + (size_t)bh * L_ * DH_;
    const float* vp = g_v + (size_t)bh * L_ * DH_;

    // Load Q tile
    #pragma unroll
    for (int r = 0; r < 4; r++) {
        int idx = t + r * 256;            // float4 index, 0..1023
        int row = idx >> 4;
        int col = (idx & 15) << 2;
        *(float4*)&Qs[row * 68 + col] =
            *(const float4*)(qp + (size_t)(l0 + row) * DH_ + col);
    }

    float Ot[4][4] = {};
    float mrow[4], lrow[4];
    #pragma unroll
    for (int i = 0; i < 4; i++) { mrow[i] = -1e30f; lrow[i] = 0.f; }

    const int ntiles = qt + 1;
    for (int tt = 0; tt < ntiles; tt++) {
        const int m0    = tt * 64;
        const int jbase = L_ - 64 - l0 + m0;

        // ---- QE strip: two 64-column halves ----
        #pragma unroll
        for (int half = 0; half < 2; half++) {
            __syncthreads();   // prior consumers of Bs / QEb done
            #pragma unroll
            for (int r = 0; r < 4; r++) {
                int idx = t + r * 256;
                int row = idx >> 4;
                int col = (idx & 15) << 2;
                int er  = jbase + half * 64 + row;
                er = (er < L_) ? er : (L_ - 1);   // OOB rows are masked later
                *(float4*)&Bs[row * 72 + col] =
                    *(const float4*)(E + (size_t)er * DH_ + col);
            }
            __syncthreads();
            float qe[4][4] = {};
            tile_dot(&Qs[(tr << 2) * 68], 68, &Bs[(tc << 2) * 72], 72, qe);
            #pragma unroll
            for (int i = 0; i < 4; i++)
                #pragma unroll
                for (int j = 0; j < 4; j++)
                    QEb[((tr << 2) + i) * 132 + half * 64 + (tc << 2) + j] = qe[i][j];
        }

        // ---- K tile, S = Q K^T + gather(QE) ----
        __syncthreads();
        #pragma unroll
        for (int r = 0; r < 4; r++) {
            int idx = t + r * 256;
            int row = idx >> 4;
            int col = (idx & 15) << 2;
            *(float4*)&Bs[row * 72 + col] =
                *(const float4*)(kp + (size_t)(m0 + row) * DH_ + col);
        }
        __syncthreads();

        float sacc[4][4] = {};
        tile_dot(&Qs[(tr << 2) * 68], 68, &Bs[(tc << 2) * 72], 72, sacc);

        #pragma unroll
        for (int i = 0; i < 4; i++) {
            int li = (tr << 2) + i;
            int l  = l0 + li;
            #pragma unroll
            for (int j = 0; j < 4; j++) {
                int mi = (tc << 2) + j;
                int m  = m0 + mi;
                float sv = (sacc[i][j] + QEb[li * 132 + 63 - li + mi]) * 0.125f;
                sacc[i][j] = (m <= l) ? sv : -1e30f;
            }
        }

        __syncthreads();   // all QEb gathers + K reads complete

        // ---- V tile load (Bs free now) ----
        #pragma unroll
        for (int r = 0; r < 4; r++) {
            int idx = t + r * 256;
            int row = idx >> 4;
            int col = (idx & 15) << 2;
            *(float4*)&Bs[row * 72 + col] =
                *(const float4*)(vp + (size_t)(m0 + row) * DH_ + col);
        }

        // ---- online softmax; write P into QEb cols 0..63 ----
        #pragma unroll
        for (int i = 0; i < 4; i++) {
            float mx = fmaxf(fmaxf(sacc[i][0], sacc[i][1]),
                             fmaxf(sacc[i][2], sacc[i][3]));
            #pragma unroll
            for (int off = 8; off > 0; off >>= 1)
                mx = fmaxf(mx, __shfl_xor_sync(0xffffffffu, mx, off));
            float mnew = fmaxf(mrow[i], mx);
            float corr = __expf(mrow[i] - mnew);
            float psum = 0.f;
            #pragma unroll
            for (int j = 0; j < 4; j++) {
                float p = __expf(sacc[i][j] - mnew);
                QEb[((tr << 2) + i) * 132 + (tc << 2) + j] = p;
                psum += p;
            }
            #pragma unroll
            for (int off = 8; off > 0; off >>= 1)
                psum += __shfl_xor_sync(0xffffffffu, psum, off);
            lrow[i] = lrow[i] * corr + psum;
            mrow[i] = mnew;
            #pragma unroll
            for (int j = 0; j < 4; j++) Ot[i][j] *= corr;
        }

        __syncthreads();   // P + V visible

        // ---- O += P @ V ----
        #pragma unroll
        for (int kk = 0; kk < 64; kk += 4) {
            float p[4][4], vv[4][4];
            #pragma unroll
            for (int i = 0; i < 4; i++) {
                float4 x = *(const float4*)&QEb[((tr << 2) + i) * 132 + kk];
                p[i][0] = x.x; p[i][1] = x.y; p[i][2] = x.z; p[i][3] = x.w;
            }
            #pragma unroll
            for (int mm = 0; mm < 4; mm++) {
                float4 x = *(const float4*)&Bs[(kk + mm) * 72 + (tc << 2)];
                vv[mm][0] = x.x; vv[mm][1] = x.y; vv[mm][2] = x.z; vv[mm][3] = x.w;
            }
            #pragma unroll
            for (int i = 0; i < 4; i++)
                #pragma unroll
                for (int j = 0; j < 4; j++)
                    #pragma unroll
                    for (int mm = 0; mm < 4; mm++)
                        Ot[i][j] = fmaf(p[i][mm], vv[mm][j], Ot[i][j]);
        }
    }

    float* op = g_o + (size_t)bh * L_ * DH_;
    #pragma unroll
    for (int i = 0; i < 4; i++) {
        float inv = 1.0f / lrow[i];
        int row = l0 + (tr << 2) + i;
        #pragma unroll
        for (int j = 0; j < 4; j++)
            op[(size_t)row * DH_ + (tc << 2) + j] = Ot[i][j] * inv;
    }
}

// ---------------------------------------------------------------------------
extern "C" void kernel_launch(void* const* d_in, const int* in_sizes, int n_in,
                              void* d_out, int out_size)
{
    const float* Q  = (const float*)d_in[0];
    const float* K  = (const float*)d_in[1];
    const float* V  = (const float*)d_in[2];
    // d_in[3] = mask (causal, known analytically) - unused
    const float* Wq = (const float*)d_in[4];
    const float* bq = (const float*)d_in[5];
    const float* Wk = (const float*)d_in[6];
    const float* bk = (const float*)d_in[7];
    const float* Wv = (const float*)d_in[8];
    const float* bv = (const float*)d_in[9];
    const float* Wf = (const float*)d_in[10];
    const float* bf = (const float*)d_in[11];
    const float* E  = (const float*)d_in[12];
    // d_in[13] = H (known constant 8) - unused
    float* out = (float*)d_out;

    (void)in_sizes; (void)n_in; (void)out_size;

    dim3 gproj(NTOK / 64, D_ / 64, 3);
    proj_kernel<<<gproj, 256>>>(Q, K, V, Wq, Wk, Wv, bq, bk, bv);

    const int smem_attn = 64 * (68 + 72 + 132) * (int)sizeof(float);  // 69632 B
    cudaFuncSetAttribute(attn_kernel, cudaFuncAttributeMaxDynamicSharedMemorySize,
                         smem_attn);
    dim3 gattn(L_ / 64, B_ * H_);
    attn_kernel<<<gattn, 256, smem_attn>>>(E);

    dim3 gfc(NTOK / 64, D_ / 64);
    fc_kernel<<<gfc, 256>>>(Wf, bf, out);
}